// round 15
// baseline (speedup 1.0000x reference)
#include <cuda_runtime.h>
#include <cstdint>

#define CROP 8
#define W    512
#define CW   496
#define TX   16
#define TY   16
#define NT   768               /* 256 pixels x 3 channels */
#define SWP  23                /* staged px width (1 extra left px for alignment) */
#define SWF  70                /* padded row stride in floats (69 data + 1 pad) */
#define SH   22                /* staged px height */
#define TILEF (SH*SWF)         /* 1540 floats per tile */
#define TILE2 (TILEF/2)        /* 770 float2 */
#define PLANE  (W*W*3)

__device__ double g_cl, g_gx, g_gy;

__global__ void k_init() { g_cl = 0.0; g_gx = 0.0; g_gy = 0.0; }

__device__ __forceinline__ int k_epoch(int e) {
  if (e < 200) return 0;
  if (e < 2300) return ((e - 200) / 100) * 2;
  return 44;
}

// du/dv per slot s (view n = s + (s>=24)): du = n/7-3, dv = n%7-3
__constant__ float2 c_duv[48] = {
  {-3,-3},{-3,-2},{-3,-1},{-3,0},{-3,1},{-3,2},{-3,3},
  {-2,-3},{-2,-2},{-2,-1},{-2,0},{-2,1},{-2,2},{-2,3},
  {-1,-3},{-1,-2},{-1,-1},{-1,0},{-1,1},{-1,2},{-1,3},
  { 0,-3},{ 0,-2},{ 0,-1},        { 0,1},{ 0,2},{ 0,3},
  { 1,-3},{ 1,-2},{ 1,-1},{ 1,0},{ 1,1},{ 1,2},{ 1,3},
  { 2,-3},{ 2,-2},{ 2,-1},{ 2,0},{ 2,1},{ 2,2},{ 2,3},
  { 3,-3},{ 3,-2},{ 3,-1},{ 3,0},{ 3,1},{ 3,2},{ 3,3}
};

// ascending bitonic sort, fully unrolled (numerics proven rounds 3-4)
template <int N>
__device__ __forceinline__ void bsort(float (&a)[N]) {
#pragma unroll
  for (int k = 2; k <= N; k <<= 1) {
#pragma unroll
    for (int j = k >> 1; j > 0; j >>= 1) {
#pragma unroll
      for (int i = 0; i < N; i++) {
        int l = i ^ j;
        if (l > i) {
          float x = a[i], y = a[l];
          float lo = fminf(x, y), hi = fmaxf(x, y);
          bool up = ((i & k) == 0);
          a[i] = up ? lo : hi;
          a[l] = up ? hi : lo;
        }
      }
    }
  }
}

__global__ __launch_bounds__(NT, 1)
void k_main(const float* __restrict__ pred, const float* __restrict__ xin,
            const int* __restrict__ ep) {
  __shared__ float stage[6 * TILEF];   /* 36,960 B: 3 pair-buffers */
  __shared__ float red[NT / 32];

  const int tid = threadIdx.x;
  const int ch  = tid >> 8;            // 0..2
  const int pix = tid & 255;
  const int lx = pix & 15, ly = pix >> 4;
  const int gx0 = CROP + blockIdx.x * TX;
  const int gy0 = CROP + blockIdx.y * TY;
  const int b = blockIdx.z;
  const int gx = gx0 + lx, gy = gy0 + ly;
  const int row0 = gy0 - 3;
  const int colL = gx0 - 4;            // left edge of staged region (px)
  const float* xb = xin + (size_t)b * 49 * PLANE;

  const float p = __ldg(pred + ((size_t)b * W + gy) * W + gx);
  const float cen = __ldg(xb + (size_t)24 * PLANE + ((size_t)gy * W + gx) * 3 + ch);
  const float fgy = (float)gy, fgx = (float)gx;
  const int epoch = ep ? ep[0] : 1000;
  const int K = 49 - k_epoch(epoch);

  // ---- staging geometry: thread t copies float2 slot t (and slot 768+t for t<2)
  const int q0 = tid;
  const int r0 = q0 / 35, k0 = q0 - 35 * r0;
  const uint32_t off0 = (uint32_t)(row0 + r0) * (W * 3) + (uint32_t)(colL * 3 + 2 * k0);
  const bool ex = (tid < 2);
  const uint32_t off1 = (uint32_t)(row0 + 21) * (W * 3) + (uint32_t)(colL * 3 + 2 * (33 + tid));
  float2* const stg2 = (float2*)stage;

  float loc[48];
  float2 ra, rb, rxa, rxb;   // prefetch regs: 2 views (+extra slot)

  // ---- prologue: load+store pair 0, load pair 1 into regs ----
  {
    const float* pl0 = xb;                      // slot 0 -> view 0
    const float* pl1 = xb + (size_t)PLANE;      // slot 1 -> view 1
    float2 a0 = *(const float2*)(pl0 + off0);
    float2 b0 = *(const float2*)(pl1 + off0);
    float2 a1 = ex ? *(const float2*)(pl0 + off1) : a0;
    float2 b1 = ex ? *(const float2*)(pl1 + off1) : b0;
    stg2[0 * TILE2 + q0] = a0;
    stg2[1 * TILE2 + q0] = b0;
    if (ex) { stg2[0 * TILE2 + 768 + tid] = a1; stg2[1 * TILE2 + 768 + tid] = b1; }
    const float* pl2 = xb + (size_t)2 * PLANE;  // slot 2 -> view 2
    const float* pl3 = xb + (size_t)3 * PLANE;  // slot 3 -> view 3
    ra = *(const float2*)(pl2 + off0);
    rb = *(const float2*)(pl3 + off0);
    rxa = ex ? *(const float2*)(pl2 + off1) : ra;
    rxb = ex ? *(const float2*)(pl3 + off1) : rb;
  }

  // ---- pipelined loop: iter j: sync; compute pair j-1; store pair j+1; LDG pair j+2
#pragma unroll
  for (int j = 0; j <= 24; j++) {
    __syncthreads();

    if (j >= 1) {   // compute pair j-1 (slots s, s+1), staged two iterations ago
#pragma unroll
      for (int e = 0; e < 2; e++) {
        const int s = 2 * (j - 1) + e;
        float2 duv = c_duv[s];
        float ty = __fadd_rn(fgy, __fmul_rn(p, duv.x));
        float tx = __fadd_rn(fgx, __fmul_rn(p, duv.y));
        float fy = floorf(ty), fx = floorf(tx);
        float wy = ty - fy, wx = tx - fx;
        int iy = (int)fy - row0;
        int ix = (int)fx - colL;
        const float* stg = stage + (s % 6) * TILEF;
        int base = iy * SWF + ix * 3 + ch;
        float v00 = stg[base],       v01 = stg[base + 3];
        float v10 = stg[base + SWF], v11 = stg[base + SWF + 3];
        float a0 = v00 + wx * (v01 - v00);
        float a1 = v10 + wx * (v11 - v10);
        float r  = a0 + wy * (a1 - a0);
        loc[s] = fabsf(r - cen);
      }
    }

    if (j <= 22) {  // store pair j+1 (regs loaded at iter j-1; covered by compute above)
      const int sA = 2 * (j + 1);
      stg2[(sA % 6) * TILE2 + q0] = ra;
      stg2[((sA + 1) % 6) * TILE2 + q0] = rb;
      if (ex) {
        stg2[(sA % 6) * TILE2 + 768 + tid] = rxa;
        stg2[((sA + 1) % 6) * TILE2 + 768 + tid] = rxb;
      }
    }

    if (j <= 21) {  // issue LDGs for pair j+2
      const int sA = 2 * (j + 2);
      const int nA = sA + (sA >= 24 ? 1 : 0);
      const int nB = sA + 1 + (sA + 1 >= 24 ? 1 : 0);
      const float* pl0 = xb + (size_t)nA * PLANE;
      const float* pl1 = xb + (size_t)nB * PLANE;
      ra = *(const float2*)(pl0 + off0);
      rb = *(const float2*)(pl1 + off0);
      if (ex) {
        rxa = *(const float2*)(pl0 + off1);
        rxb = *(const float2*)(pl1 + off1);
      }
    }
  }

  // ---------------- phase 2: rank select + masked sum ----------------
  float A[32], B[16];
#pragma unroll
  for (int s = 0; s < 32; s++) A[s] = loc[s];
#pragma unroll
  for (int s = 0; s < 16; s++) B[s] = loc[32 + s];
  bsort<32>(A);
  bsort<16>(B);

  float mysum = 0.f;
  if (K == 33) {
    // t = rank-32 (1-indexed) of A(32) U B(16): min over i+j=32 of max(A_i,B_j)
    float t = A[31];
#pragma unroll
    for (int i2 = 16; i2 <= 31; i2++) t = fminf(t, fmaxf(A[i2 - 1], B[31 - i2]));
    float s0 = 0.f, s1 = 0.f;
#pragma unroll
    for (int s = 0; s < 16; s++) { s0 += A[s]; s1 += A[16 + s] <= t ? A[16 + s] : 0.f; }
#pragma unroll
    for (int s = 0; s < 16; s++) s1 += (B[s] <= t) ? B[s] : 0.f;
    mysum = s0 + s1;
  } else {
    // generic rank r = K-1 among 48 non-center values (uniform branch, local scratch)
    float lb[48];
#pragma unroll
    for (int s = 0; s < 32; s++) lb[s] = A[s];
#pragma unroll
    for (int s = 0; s < 16; s++) lb[32 + s] = B[s];
    int r = K - 1;
    float t = 3.0e38f;
    for (int a = 0; a < 48; a++) {
      float va = lb[a];
      int cnt = 0;
      for (int q = 0; q < 48; q++) cnt += (lb[q] <= va) ? 1 : 0;
      if (cnt >= r) t = fminf(t, va);
    }
    for (int a = 0; a < 48; a++) mysum += (lb[a] <= t) ? lb[a] : 0.f;
  }

  // block reduce -> one double atomic
#pragma unroll
  for (int o = 16; o > 0; o >>= 1) mysum += __shfl_down_sync(0xffffffffu, mysum, o);
  if ((tid & 31) == 0) red[tid >> 5] = mysum;
  __syncthreads();
  if (tid == 0) {
    float tot = 0.f;
    for (int w2 = 0; w2 < NT / 32; w2++) tot += red[w2];
    atomicAdd(&g_cl, (double)tot);
  }
}

// ---------------- edge-aware smoothness, split by direction ----------------
__global__ void k_gradx(const float* __restrict__ pred, const float* __restrict__ xin) {
  int idx = blockIdx.x * 256 + threadIdx.x;
  float sx = 0.f;
  if (idx < 2 * CW * CW) {
    int b = idx / (CW * CW);
    int rem = idx - b * (CW * CW);
    int y = CROP + rem / CW;
    int x = CROP + rem % CW;
    if (x < CROP + CW - 1) {
      const float* I = xin + ((size_t)b * 49 + 24) * PLANE;
      const float* D = pred + (size_t)b * W * W;
      size_t o = (size_t)y * W + x;
      float a = fabsf(I[(o + 1) * 3] - I[o * 3]) +
                fabsf(I[(o + 1) * 3 + 1] - I[o * 3 + 1]) +
                fabsf(I[(o + 1) * 3 + 2] - I[o * 3 + 2]);
      sx = expf(-50.f * a) * fabsf(D[o + 1] - D[o]);
    }
  }
#pragma unroll
  for (int o2 = 16; o2 > 0; o2 >>= 1) sx += __shfl_down_sync(0xffffffffu, sx, o2);
  __shared__ float rx[8];
  int tid = threadIdx.x;
  if ((tid & 31) == 0) rx[tid >> 5] = sx;
  __syncthreads();
  if (tid == 0) {
    float a = 0.f;
    for (int w2 = 0; w2 < 8; w2++) a += rx[w2];
    atomicAdd(&g_gx, (double)a);
  }
}

__global__ void k_grady(const float* __restrict__ pred, const float* __restrict__ xin) {
  int idx = blockIdx.x * 256 + threadIdx.x;
  float sy = 0.f;
  if (idx < 2 * CW * CW) {
    int b = idx / (CW * CW);
    int rem = idx - b * (CW * CW);
    int y = CROP + rem / CW;
    int x = CROP + rem % CW;
    if (y < CROP + CW - 1) {
      const float* I = xin + ((size_t)b * 49 + 24) * PLANE;
      const float* D = pred + (size_t)b * W * W;
      size_t o = (size_t)y * W + x;
      float a = fabsf(I[(o + W) * 3] - I[o * 3]) +
                fabsf(I[(o + W) * 3 + 1] - I[o * 3 + 1]) +
                fabsf(I[(o + W) * 3 + 2] - I[o * 3 + 2]);
      sy = expf(-50.f * a) * fabsf(D[o + W] - D[o]);
    }
  }
#pragma unroll
  for (int o2 = 16; o2 > 0; o2 >>= 1) sy += __shfl_down_sync(0xffffffffu, sy, o2);
  __shared__ float ry[8];
  int tid = threadIdx.x;
  if ((tid & 31) == 0) ry[tid >> 5] = sy;
  __syncthreads();
  if (tid == 0) {
    float c = 0.f;
    for (int w2 = 0; w2 < 8; w2++) c += ry[w2];
    atomicAdd(&g_gy, (double)c);
  }
}

__global__ void k_fin(const int* __restrict__ ep, float* __restrict__ out) {
  int epoch = ep ? ep[0] : 1000;
  int K = 49 - k_epoch(epoch);
  double mcl = g_cl / ((double)K * 6.0 * 496.0 * 496.0);
  double den = 2.0 * 496.0 * 495.0;
  double gl = 0.5 * (g_gx / den + g_gy / den);
  out[0] = (float)(mcl + 0.1 * gl);
}

extern "C" void kernel_launch(void* const* d_in, const int* in_sizes, int n_in,
                              void* d_out, int out_size) {
  const float* pred = (const float*)d_in[0];
  const float* x    = (const float*)d_in[1];
  const int*   ep   = (n_in >= 3) ? (const int*)d_in[2] : nullptr;

  k_init<<<1, 1>>>();
  k_gradx<<<(2 * CW * CW + 255) / 256, 256>>>(pred, x);
  k_grady<<<(2 * CW * CW + 255) / 256, 256>>>(pred, x);
  dim3 grid(31, 31, 2);
  k_main<<<grid, NT>>>(pred, x, ep);
  k_fin<<<1, 1>>>(ep, (float*)d_out);
}

// round 16
// speedup vs baseline: 1.7397x; 1.7397x over previous
#include <cuda_runtime.h>
#include <cstdint>

#define CROP 8
#define W    512
#define CW   496
#define TX   16
#define TY   16
#define NT   768               /* 256 pixels x 3 channels */
#define TILE_W   72            /* floats per staged row (16B aligned) */
#define TILE_ROWS 22
#define TILEF (TILE_ROWS*TILE_W)   /* 1584 floats per view tile */
#define TILE4 (TILEF/4)            /* 396 float4 per tile */
#define GROUPF (16*TILEF)          /* 25344 floats per 16-view group */
#define GROUP4 (16*TILE4)          /* 6336 float4 per group */
#define PLANE  (W*W*3)
#define RED_OFF (2*GROUPF)
#define SMEM_FLOATS (RED_OFF + 32)
#define SMEM_BYTES (SMEM_FLOATS*4)  /* 202,880 B */

__device__ double g_cl, g_gx, g_gy;

__global__ void k_init() { g_cl = 0.0; g_gx = 0.0; g_gy = 0.0; }

__device__ __forceinline__ int k_epoch(int e) {
  if (e < 200) return 0;
  if (e < 2300) return ((e - 200) / 100) * 2;
  return 44;
}

// du/dv per slot s (view n = s + (s>=24)): du = n/7-3, dv = n%7-3
__constant__ float2 c_duv[48] = {
  {-3,-3},{-3,-2},{-3,-1},{-3,0},{-3,1},{-3,2},{-3,3},
  {-2,-3},{-2,-2},{-2,-1},{-2,0},{-2,1},{-2,2},{-2,3},
  {-1,-3},{-1,-2},{-1,-1},{-1,0},{-1,1},{-1,2},{-1,3},
  { 0,-3},{ 0,-2},{ 0,-1},        { 0,1},{ 0,2},{ 0,3},
  { 1,-3},{ 1,-2},{ 1,-1},{ 1,0},{ 1,1},{ 1,2},{ 1,3},
  { 2,-3},{ 2,-2},{ 2,-1},{ 2,0},{ 2,1},{ 2,2},{ 2,3},
  { 3,-3},{ 3,-2},{ 3,-1},{ 3,0},{ 3,1},{ 3,2},{ 3,3}
};

// ascending bitonic sort, fully unrolled (numerics proven rounds 3-4)
template <int N>
__device__ __forceinline__ void bsort(float (&a)[N]) {
#pragma unroll
  for (int k = 2; k <= N; k <<= 1) {
#pragma unroll
    for (int j = k >> 1; j > 0; j >>= 1) {
#pragma unroll
      for (int i = 0; i < N; i++) {
        int l = i ^ j;
        if (l > i) {
          float x = a[i], y = a[l];
          float lo = fminf(x, y), hi = fmaxf(x, y);
          bool up = ((i & k) == 0);
          a[i] = up ? lo : hi;
          a[l] = up ? hi : lo;
        }
      }
    }
  }
}

// issue cp.async 16B copies for one 16-view group (one commit group)
__device__ __forceinline__ void stage_group(
    int g, int buf, int tid, const float* __restrict__ xb,
    int row0, uint32_t cbase, uint32_t smem_base) {
  const int g16 = g * 16;
#pragma unroll
  for (int j = 0; j < 9; j++) {
    int q = tid + j * NT;
    if (j < 8 || tid < GROUP4 - 8 * NT) {   // q < 6336
      int v = q / TILE4;           // view within group
      int w = q - TILE4 * v;       // float4 index within tile
      int r = w / 18;              // staged row
      int c4 = w - 18 * r;         // float4 within row
      int s = g16 + v;
      int n = s + (s >= 24 ? 1 : 0);
      const float* src = xb + (size_t)n * PLANE +
                         (uint32_t)(row0 + r) * (uint32_t)(W * 3) + cbase + 4u * c4;
      uint32_t dst = smem_base + (uint32_t)(buf * GROUPF + v * TILEF) * 4u +
                     (uint32_t)w * 16u;
      asm volatile("cp.async.cg.shared.global [%0], [%1], 16;\n"
                   :: "r"(dst), "l"(src));
    }
  }
  asm volatile("cp.async.commit_group;\n" ::);
}

__global__ __launch_bounds__(NT, 1)
void k_main(const float* __restrict__ pred, const float* __restrict__ xin,
            const int* __restrict__ ep) {
  extern __shared__ float stage[];           // 2 group buffers + red
  float* red = stage + RED_OFF;

  const int tid = threadIdx.x;
  const int ch  = tid >> 8;                  // 0..2
  const int pix = tid & 255;
  const int lx = pix & 15, ly = pix >> 4;
  const int gx0 = CROP + blockIdx.x * TX;
  const int gy0 = CROP + blockIdx.y * TY;
  const int b = blockIdx.z;
  const int gx = gx0 + lx, gy = gy0 + ly;
  const int row0 = gy0 - 3;
  const int colL = gx0 - 3;                  // left staged px (logical)
  const uint32_t colLf = (uint32_t)(colL * 3);
  const uint32_t cbase = colLf & ~3u;        // 16B-aligned float index
  const int dch = (int)(colLf & 3u) + ch;    // alignment shift folded into channel
  const float* xb = xin + (size_t)b * 49 * PLANE;
  const uint32_t smem_base = (uint32_t)__cvta_generic_to_shared(stage);

  // stage group 0 first so DMA overlaps the scalar prologue
  stage_group(0, 0, tid, xb, row0, cbase, smem_base);

  const float p = __ldg(pred + ((size_t)b * W + gy) * W + gx);
  const float cen = __ldg(xb + (size_t)24 * PLANE + ((size_t)gy * W + gx) * 3 + ch);
  const float fgy = (float)gy, fgx = (float)gx;
  const int epoch = ep ? ep[0] : 1000;
  const int K = 49 - k_epoch(epoch);
  const bool fast = (K == 33);

  float T[16];
  float t17 = -1.0f;
  float total = 0.f;
  float lb[48];    // only written in (never-taken) generic-K path

  for (int g = 0; g < 3; g++) {
    asm volatile("cp.async.wait_group 0;\n" ::);   // group g complete
    __syncthreads();   // everyone sees group g; done reading buf[(g-1)&1]

    if (g < 2) stage_group(g + 1, (g + 1) & 1, tid, xb, row0, cbase, smem_base);

    const float* buf = stage + (g & 1) * GROUPF;
    const int g16 = g * 16;
    float v[16];
#pragma unroll
    for (int i = 0; i < 16; i++) {
      int s = g16 + i;
      float2 duv = c_duv[s];
      float tyy = __fadd_rn(fgy, __fmul_rn(p, duv.x));
      float txx = __fadd_rn(fgx, __fmul_rn(p, duv.y));
      float fy = floorf(tyy), fx = floorf(txx);
      float wy = tyy - fy, wx = txx - fx;
      int iy = (int)fy - row0;
      int ix = (int)fx - colL;
      const float* stg = buf + i * TILEF;
      int base = iy * TILE_W + ix * 3 + dch;
      float v00 = stg[base],          v01 = stg[base + 3];
      float v10 = stg[base + TILE_W], v11 = stg[base + TILE_W + 3];
      float a0 = v00 + wx * (v01 - v00);
      float a1 = v10 + wx * (v11 - v10);
      float rr = a0 + wy * (a1 - a0);
      float av = fabsf(rr - cen);
      v[i] = av;
      total += av;
      if (!fast) lb[s] = av;
    }

    bsort<16>(v);   // ascending

    if (g == 0) {
#pragma unroll
      for (int i = 0; i < 16; i++) T[i] = v[15 - i];   // descending
    } else {
      // half-cleaner: T desc ++ v asc is bitonic; C=top-16, R=rest
      float R[16];
#pragma unroll
      for (int i = 0; i < 16; i++) {
        float c = fmaxf(T[i], v[i]);
        R[i] = fminf(T[i], v[i]);
        T[i] = c;
      }
      float rmax = R[0];
#pragma unroll
      for (int i = 1; i < 16; i++) rmax = fmaxf(rmax, R[i]);
      t17 = fmaxf(t17, rmax);
      // bitonic merge: sort T (bitonic) descending
#pragma unroll
      for (int d = 8; d > 0; d >>= 1) {
#pragma unroll
        for (int i = 0; i < 16; i++) {
          if ((i & d) == 0) {
            int l = i | d;
            float hi = fmaxf(T[i], T[l]);
            float lo = fminf(T[i], T[l]);
            T[i] = hi; T[l] = lo;
          }
        }
      }
    }
  }

  // ---------------- masked-sum epilogue ----------------
  float mysum;
  if (fast) {
    // t17 = max of all rejected = 17th largest of 48 = rank-32 smallest.
    // All elements strictly greater than t17 are in T (top-16).
    float t = t17;
    float sub = 0.f;
#pragma unroll
    for (int i = 0; i < 16; i++) sub += (T[i] > t) ? T[i] : 0.f;
    mysum = total - sub;
  } else {
    // generic rank r = K-1 among 48 non-center values (uniform, never @1000)
    int r = K - 1;
    float t = 3.0e38f;
    for (int a = 0; a < 48; a++) {
      float va = lb[a];
      int cnt = 0;
      for (int q = 0; q < 48; q++) cnt += (lb[q] <= va) ? 1 : 0;
      if (cnt >= r) t = fminf(t, va);
    }
    mysum = 0.f;
    for (int a = 0; a < 48; a++) mysum += (lb[a] <= t) ? lb[a] : 0.f;
  }

  // block reduce -> one double atomic
#pragma unroll
  for (int o = 16; o > 0; o >>= 1) mysum += __shfl_down_sync(0xffffffffu, mysum, o);
  if ((tid & 31) == 0) red[tid >> 5] = mysum;
  __syncthreads();
  if (tid == 0) {
    float tot = 0.f;
    for (int w2 = 0; w2 < NT / 32; w2++) tot += red[w2];
    atomicAdd(&g_cl, (double)tot);
  }
}

// ---------------- edge-aware smoothness, split by direction ----------------
__global__ void k_gradx(const float* __restrict__ pred, const float* __restrict__ xin) {
  int idx = blockIdx.x * 256 + threadIdx.x;
  float sx = 0.f;
  if (idx < 2 * CW * CW) {
    int b = idx / (CW * CW);
    int rem = idx - b * (CW * CW);
    int y = CROP + rem / CW;
    int x = CROP + rem % CW;
    if (x < CROP + CW - 1) {
      const float* I = xin + ((size_t)b * 49 + 24) * PLANE;
      const float* D = pred + (size_t)b * W * W;
      size_t o = (size_t)y * W + x;
      float a = fabsf(I[(o + 1) * 3] - I[o * 3]) +
                fabsf(I[(o + 1) * 3 + 1] - I[o * 3 + 1]) +
                fabsf(I[(o + 1) * 3 + 2] - I[o * 3 + 2]);
      sx = expf(-50.f * a) * fabsf(D[o + 1] - D[o]);
    }
  }
#pragma unroll
  for (int o2 = 16; o2 > 0; o2 >>= 1) sx += __shfl_down_sync(0xffffffffu, sx, o2);
  __shared__ float rx[8];
  int tid = threadIdx.x;
  if ((tid & 31) == 0) rx[tid >> 5] = sx;
  __syncthreads();
  if (tid == 0) {
    float a = 0.f;
    for (int w2 = 0; w2 < 8; w2++) a += rx[w2];
    atomicAdd(&g_gx, (double)a);
  }
}

__global__ void k_grady(const float* __restrict__ pred, const float* __restrict__ xin) {
  int idx = blockIdx.x * 256 + threadIdx.x;
  float sy = 0.f;
  if (idx < 2 * CW * CW) {
    int b = idx / (CW * CW);
    int rem = idx - b * (CW * CW);
    int y = CROP + rem / CW;
    int x = CROP + rem % CW;
    if (y < CROP + CW - 1) {
      const float* I = xin + ((size_t)b * 49 + 24) * PLANE;
      const float* D = pred + (size_t)b * W * W;
      size_t o = (size_t)y * W + x;
      float a = fabsf(I[(o + W) * 3] - I[o * 3]) +
                fabsf(I[(o + W) * 3 + 1] - I[o * 3 + 1]) +
                fabsf(I[(o + W) * 3 + 2] - I[o * 3 + 2]);
      sy = expf(-50.f * a) * fabsf(D[o + W] - D[o]);
    }
  }
#pragma unroll
  for (int o2 = 16; o2 > 0; o2 >>= 1) sy += __shfl_down_sync(0xffffffffu, sy, o2);
  __shared__ float ry[8];
  int tid = threadIdx.x;
  if ((tid & 31) == 0) ry[tid >> 5] = sy;
  __syncthreads();
  if (tid == 0) {
    float c = 0.f;
    for (int w2 = 0; w2 < 8; w2++) c += ry[w2];
    atomicAdd(&g_gy, (double)c);
  }
}

__global__ void k_fin(const int* __restrict__ ep, float* __restrict__ out) {
  int epoch = ep ? ep[0] : 1000;
  int K = 49 - k_epoch(epoch);
  double mcl = g_cl / ((double)K * 6.0 * 496.0 * 496.0);
  double den = 2.0 * 496.0 * 495.0;
  double gl = 0.5 * (g_gx / den + g_gy / den);
  out[0] = (float)(mcl + 0.1 * gl);
}

extern "C" void kernel_launch(void* const* d_in, const int* in_sizes, int n_in,
                              void* d_out, int out_size) {
  const float* pred = (const float*)d_in[0];
  const float* x    = (const float*)d_in[1];
  const int*   ep   = (n_in >= 3) ? (const int*)d_in[2] : nullptr;

  cudaFuncSetAttribute(k_main, cudaFuncAttributeMaxDynamicSharedMemorySize, SMEM_BYTES);

  k_init<<<1, 1>>>();
  k_gradx<<<(2 * CW * CW + 255) / 256, 256>>>(pred, x);
  k_grady<<<(2 * CW * CW + 255) / 256, 256>>>(pred, x);
  dim3 grid(31, 31, 2);
  k_main<<<grid, NT, SMEM_BYTES>>>(pred, x, ep);
  k_fin<<<1, 1>>>(ep, (float*)d_out);
}

// round 17
// speedup vs baseline: 1.8285x; 1.0511x over previous
#include <cuda_runtime.h>
#include <cstdint>

#define CROP 8
#define W    512
#define CW   496
#define TX   16
#define TY   16
#define NT   768               /* 256 pixels x 3 channels */
#define TILE_W   72            /* floats per staged row (16B aligned) */
#define TILE_ROWS 22
#define TILEF (TILE_ROWS*TILE_W)   /* 1584 floats per view tile */
#define TILE4 (TILEF/4)            /* 396 float4 per tile */
#define GROUPF (16*TILEF)          /* 25344 floats per 16-view group */
#define GROUP4 (16*TILE4)          /* 6336 float4 per group */
#define PLANE  (W*W*3)
#define RED_OFF (2*GROUPF)
#define SMEM_FLOATS (RED_OFF + 32)
#define SMEM_BYTES (SMEM_FLOATS*4)  /* 202,880 B */

__device__ double g_cl, g_gx, g_gy;

__global__ void k_init() { g_cl = 0.0; g_gx = 0.0; g_gy = 0.0; }

__device__ __forceinline__ int k_epoch(int e) {
  if (e < 200) return 0;
  if (e < 2300) return ((e - 200) / 100) * 2;
  return 44;
}

// du/dv per slot s (view n = s + (s>=24)): du = n/7-3, dv = n%7-3
__constant__ float2 c_duv[48] = {
  {-3,-3},{-3,-2},{-3,-1},{-3,0},{-3,1},{-3,2},{-3,3},
  {-2,-3},{-2,-2},{-2,-1},{-2,0},{-2,1},{-2,2},{-2,3},
  {-1,-3},{-1,-2},{-1,-1},{-1,0},{-1,1},{-1,2},{-1,3},
  { 0,-3},{ 0,-2},{ 0,-1},        { 0,1},{ 0,2},{ 0,3},
  { 1,-3},{ 1,-2},{ 1,-1},{ 1,0},{ 1,1},{ 1,2},{ 1,3},
  { 2,-3},{ 2,-2},{ 2,-1},{ 2,0},{ 2,1},{ 2,2},{ 2,3},
  { 3,-3},{ 3,-2},{ 3,-1},{ 3,0},{ 3,1},{ 3,2},{ 3,3}
};

// ascending bitonic sort, fully unrolled (numerics proven rounds 3-4)
template <int N>
__device__ __forceinline__ void bsort(float (&a)[N]) {
#pragma unroll
  for (int k = 2; k <= N; k <<= 1) {
#pragma unroll
    for (int j = k >> 1; j > 0; j >>= 1) {
#pragma unroll
      for (int i = 0; i < N; i++) {
        int l = i ^ j;
        if (l > i) {
          float x = a[i], y = a[l];
          float lo = fminf(x, y), hi = fmaxf(x, y);
          bool up = ((i & k) == 0);
          a[i] = up ? lo : hi;
          a[l] = up ? hi : lo;
        }
      }
    }
  }
}

// issue cp.async 16B copies for one 16-view group (one commit group)
__device__ __forceinline__ void stage_group(
    int g, int buf, int tid, const float* __restrict__ xb,
    int row0, uint32_t cbase, uint32_t smem_base) {
  const int g16 = g * 16;
#pragma unroll
  for (int j = 0; j < 9; j++) {
    int q = tid + j * NT;
    if (j < 8 || tid < GROUP4 - 8 * NT) {   // q < 6336
      int v = q / TILE4;           // view within group
      int w = q - TILE4 * v;       // float4 index within tile
      int r = w / 18;              // staged row
      int c4 = w - 18 * r;         // float4 within row
      int s = g16 + v;
      int n = s + (s >= 24 ? 1 : 0);
      const float* src = xb + (size_t)n * PLANE +
                         (uint32_t)(row0 + r) * (uint32_t)(W * 3) + cbase + 4u * c4;
      uint32_t dst = smem_base + (uint32_t)(buf * GROUPF + v * TILEF) * 4u +
                     (uint32_t)w * 16u;
      asm volatile("cp.async.cg.shared.global [%0], [%1], 16;\n"
                   :: "r"(dst), "l"(src));
    }
  }
  asm volatile("cp.async.commit_group;\n" ::);
}

__global__ __launch_bounds__(NT, 1)
void k_main(const float* __restrict__ pred, const float* __restrict__ xin,
            const int* __restrict__ ep) {
  extern __shared__ float stage[];           // 2 group buffers + red
  float* red = stage + RED_OFF;

  const int tid = threadIdx.x;
  const int ch  = tid >> 8;                  // 0..2
  const int pix = tid & 255;
  const int lx = pix & 15, ly = pix >> 4;
  const int gx0 = CROP + blockIdx.x * TX;
  const int gy0 = CROP + blockIdx.y * TY;
  const int b = blockIdx.z;
  const int gx = gx0 + lx, gy = gy0 + ly;
  const int row0 = gy0 - 3;
  const int colL = gx0 - 3;                  // left staged px (logical)
  const uint32_t colLf = (uint32_t)(colL * 3);
  const uint32_t cbase = colLf & ~3u;        // 16B-aligned float index
  const int dch = (int)(colLf & 3u) + ch;    // alignment shift folded into channel
  const float* xb = xin + (size_t)b * 49 * PLANE;
  const uint32_t smem_base = (uint32_t)__cvta_generic_to_shared(stage);

  // stage group 0 first so DMA overlaps the scalar prologue
  stage_group(0, 0, tid, xb, row0, cbase, smem_base);

  const float p = __ldg(pred + ((size_t)b * W + gy) * W + gx);
  const float cen = __ldg(xb + (size_t)24 * PLANE + ((size_t)gy * W + gx) * 3 + ch);
  const float fgy = (float)gy, fgx = (float)gx;
  const int epoch = ep ? ep[0] : 1000;
  const int K = 49 - k_epoch(epoch);
  const bool fast = (K == 33);

  float T[16];
  float t17 = -1.0f;
  float total = 0.f;

  for (int g = 0; g < 3; g++) {
    asm volatile("cp.async.wait_group 0;\n" ::);   // group g complete
    __syncthreads();   // everyone sees group g; done reading buf[(g-1)&1]

    if (g < 2) stage_group(g + 1, (g + 1) & 1, tid, xb, row0, cbase, smem_base);

    const float* buf = stage + (g & 1) * GROUPF;
    const int g16 = g * 16;
    float v[16];
#pragma unroll
    for (int i = 0; i < 16; i++) {
      int s = g16 + i;
      float2 duv = c_duv[s];
      float tyy = __fadd_rn(fgy, __fmul_rn(p, duv.x));
      float txx = __fadd_rn(fgx, __fmul_rn(p, duv.y));
      float fy = floorf(tyy), fx = floorf(txx);
      float wy = tyy - fy, wx = txx - fx;
      int iy = (int)fy - row0;
      int ix = (int)fx - colL;
      const float* stg = buf + i * TILEF;
      int base = iy * TILE_W + ix * 3 + dch;
      float v00 = stg[base],          v01 = stg[base + 3];
      float v10 = stg[base + TILE_W], v11 = stg[base + TILE_W + 3];
      float a0 = v00 + wx * (v01 - v00);
      float a1 = v10 + wx * (v11 - v10);
      float rr = a0 + wy * (a1 - a0);
      float av = fabsf(rr - cen);
      v[i] = av;
      total += av;
    }

    bsort<16>(v);   // ascending

    if (g == 0) {
#pragma unroll
      for (int i = 0; i < 16; i++) T[i] = v[15 - i];   // descending
    } else {
      // half-cleaner: T desc ++ v asc is bitonic; C=top-16, R=rest
      float R[16];
#pragma unroll
      for (int i = 0; i < 16; i++) {
        float c = fmaxf(T[i], v[i]);
        R[i] = fminf(T[i], v[i]);
        T[i] = c;
      }
      float rmax = R[0];
#pragma unroll
      for (int i = 1; i < 16; i++) rmax = fmaxf(rmax, R[i]);
      t17 = fmaxf(t17, rmax);
      // bitonic merge: sort T (bitonic) descending
#pragma unroll
      for (int d = 8; d > 0; d >>= 1) {
#pragma unroll
        for (int i = 0; i < 16; i++) {
          if ((i & d) == 0) {
            int l = i | d;
            float hi = fmaxf(T[i], T[l]);
            float lo = fminf(T[i], T[l]);
            T[i] = hi; T[l] = lo;
          }
        }
      }
    }
  }

  // ---------------- masked-sum epilogue ----------------
  float mysum;
  if (fast) {
    // t17 = max of all rejected = 17th largest of 48 = rank-32 smallest.
    // All elements strictly greater than t17 are in T (top-16).
    float t = t17;
    float sub = 0.f;
#pragma unroll
    for (int i = 0; i < 16; i++) sub += (T[i] > t) ? T[i] : 0.f;
    mysum = total - sub;
  } else {
    // generic rank r = K-1: cold path, recompute all 48 values from gmem.
    // Uniform branch; never taken at epoch 1000, kept correct for any epoch.
    float lb[48];
    for (int s = 0; s < 48; s++) {
      int n = s + (s >= 24 ? 1 : 0);
      float du = (float)(n / 7 - 3), dv = (float)(n % 7 - 3);
      float tyy = __fadd_rn(fgy, __fmul_rn(p, du));
      float txx = __fadd_rn(fgx, __fmul_rn(p, dv));
      float fy = floorf(tyy), fx = floorf(txx);
      float wy = tyy - fy, wx = txx - fx;
      int y0 = (int)fy, x0 = (int)fx;
      const float* pl = xb + (size_t)n * PLANE;
      float v00 = __ldg(pl + ((size_t)y0 * W + x0) * 3 + ch);
      float v01 = __ldg(pl + ((size_t)y0 * W + x0 + 1) * 3 + ch);
      float v10 = __ldg(pl + ((size_t)(y0 + 1) * W + x0) * 3 + ch);
      float v11 = __ldg(pl + ((size_t)(y0 + 1) * W + x0 + 1) * 3 + ch);
      float a0 = v00 + wx * (v01 - v00);
      float a1 = v10 + wx * (v11 - v10);
      float rr = a0 + wy * (a1 - a0);
      lb[s] = fabsf(rr - cen);
    }
    int r = K - 1;
    float t = 3.0e38f;
    for (int a = 0; a < 48; a++) {
      float va = lb[a];
      int cnt = 0;
      for (int q = 0; q < 48; q++) cnt += (lb[q] <= va) ? 1 : 0;
      if (cnt >= r) t = fminf(t, va);
    }
    mysum = 0.f;
    for (int a = 0; a < 48; a++) mysum += (lb[a] <= t) ? lb[a] : 0.f;
  }

  // block reduce -> one double atomic
#pragma unroll
  for (int o = 16; o > 0; o >>= 1) mysum += __shfl_down_sync(0xffffffffu, mysum, o);
  if ((tid & 31) == 0) red[tid >> 5] = mysum;
  __syncthreads();
  if (tid == 0) {
    float tot = 0.f;
    for (int w2 = 0; w2 < NT / 32; w2++) tot += red[w2];
    atomicAdd(&g_cl, (double)tot);
  }
}

// ---------------- edge-aware smoothness (fused x+y, proven R4 code) --------
__global__ void k_grad(const float* __restrict__ pred, const float* __restrict__ xin) {
  int idx = blockIdx.x * 256 + threadIdx.x;
  float sx = 0.f, sy = 0.f;
  if (idx < 2 * CW * CW) {
    int b = idx / (CW * CW);
    int rem = idx - b * (CW * CW);
    int y = CROP + rem / CW;
    int x = CROP + rem % CW;
    const float* I = xin + ((size_t)b * 49 + 24) * PLANE;
    const float* D = pred + (size_t)b * W * W;
    size_t o = (size_t)y * W + x;
    float i0 = I[o * 3], i1 = I[o * 3 + 1], i2 = I[o * 3 + 2];
    float d0 = D[o];
    if (x < CROP + CW - 1) {
      float a = fabsf(I[(o + 1) * 3] - i0) + fabsf(I[(o + 1) * 3 + 1] - i1) +
                fabsf(I[(o + 1) * 3 + 2] - i2);
      sx = expf(-50.f * a) * fabsf(D[o + 1] - d0);
    }
    if (y < CROP + CW - 1) {
      float a = fabsf(I[(o + W) * 3] - i0) + fabsf(I[(o + W) * 3 + 1] - i1) +
                fabsf(I[(o + W) * 3 + 2] - i2);
      sy = expf(-50.f * a) * fabsf(D[o + W] - d0);
    }
  }
#pragma unroll
  for (int o2 = 16; o2 > 0; o2 >>= 1) {
    sx += __shfl_down_sync(0xffffffffu, sx, o2);
    sy += __shfl_down_sync(0xffffffffu, sy, o2);
  }
  __shared__ float rx[8], ry[8];
  int tid = threadIdx.x;
  if ((tid & 31) == 0) { rx[tid >> 5] = sx; ry[tid >> 5] = sy; }
  __syncthreads();
  if (tid == 0) {
    float a = 0.f, c = 0.f;
    for (int w2 = 0; w2 < 8; w2++) { a += rx[w2]; c += ry[w2]; }
    atomicAdd(&g_gx, (double)a);
    atomicAdd(&g_gy, (double)c);
  }
}

__global__ void k_fin(const int* __restrict__ ep, float* __restrict__ out) {
  int epoch = ep ? ep[0] : 1000;
  int K = 49 - k_epoch(epoch);
  double mcl = g_cl / ((double)K * 6.0 * 496.0 * 496.0);
  double den = 2.0 * 496.0 * 495.0;
  double gl = 0.5 * (g_gx / den + g_gy / den);
  out[0] = (float)(mcl + 0.1 * gl);
}

extern "C" void kernel_launch(void* const* d_in, const int* in_sizes, int n_in,
                              void* d_out, int out_size) {
  const float* pred = (const float*)d_in[0];
  const float* x    = (const float*)d_in[1];
  const int*   ep   = (n_in >= 3) ? (const int*)d_in[2] : nullptr;

  cudaFuncSetAttribute(k_main, cudaFuncAttributeMaxDynamicSharedMemorySize, SMEM_BYTES);

  k_init<<<1, 1>>>();
  k_grad<<<(2 * CW * CW + 255) / 256, 256>>>(pred, x);
  dim3 grid(31, 31, 2);
  k_main<<<grid, NT, SMEM_BYTES>>>(pred, x, ep);
  k_fin<<<1, 1>>>(ep, (float*)d_out);
}